// round 1
// baseline (speedup 1.0000x reference)
#include <cuda_runtime.h>
#include <math.h>

// Problem: B = H = IN = 256, c = 1.
// Dead code in reference (_dead, r_point_h, Wh*/Uh*) is skipped.

#define NB 256
#define MAXN 0.996f         // (1 - 4e-3)/sqrt(c)
#define EPSN 1e-15f

// ---------------- scratch (static device globals; no runtime alloc) --------
__device__ float g_w[4][NB * NB];     // w = sinh(mlr logits) per fc, [b][cl]
__device__ float g_scale[4][NB];      // sqrt(row-sumsq of w)+1, indexed by row
__device__ float g_nz[4][NB];         // ||z_cl|| per fc
__device__ float g_coef[4][NB];       // 2*||z_cl||/cosh(r_cl)^2
__device__ float g_y2[2][NB];         // ||x_b||^2 : [0]=hidden, [1]=hyp_x

// ---------------- block reduction (256 threads) ----------------------------
__device__ __forceinline__ float brsum256(float v, float* sb) {
    const int lane = threadIdx.x & 31, wid = threadIdx.x >> 5;
    #pragma unroll
    for (int o = 16; o; o >>= 1) v += __shfl_down_sync(0xffffffffu, v, o);
    if (lane == 0) sb[wid] = v;
    __syncthreads();
    if (wid == 0) {
        float r = (lane < 8) ? sb[lane] : 0.0f;
        #pragma unroll
        for (int o = 4; o; o >>= 1) r += __shfl_down_sync(0xffu, r, o);
        if (lane == 0) sb[0] = r;
    }
    __syncthreads();
    float res = sb[0];
    __syncthreads();   // protect sb before next reuse
    return res;
}

// ---------------- K0: per-row stats ----------------------------------------
__global__ void k0_stats(const float* __restrict__ Wz_z, const float* __restrict__ Wz_r,
                         const float* __restrict__ Uz_z, const float* __restrict__ Uz_r,
                         const float* __restrict__ Wr_z, const float* __restrict__ Wr_r,
                         const float* __restrict__ Ur_z, const float* __restrict__ Ur_r,
                         const float* __restrict__ hidden, const float* __restrict__ hyp_x)
{
    __shared__ float sb[8];
    const int row = blockIdx.x;
    const int m = blockIdx.y;
    const float* p;
    if      (m == 0) p = Wz_z;
    else if (m == 1) p = Uz_z;
    else if (m == 2) p = Wr_z;
    else if (m == 3) p = Ur_z;
    else if (m == 4) p = hidden;
    else             p = hyp_x;

    float v = p[row * NB + threadIdx.x];
    float ss = brsum256(v * v, sb);
    if (threadIdx.x == 0) {
        if (m < 4) {
            const float* R;
            if      (m == 0) R = Wz_r;
            else if (m == 1) R = Uz_r;
            else if (m == 2) R = Wr_r;
            else             R = Ur_r;
            float nz = sqrtf(ss);
            g_nz[m][row] = nz;
            float ch = coshf(R[row]);
            g_coef[m][row] = 2.0f * nz / (ch * ch);
        } else {
            g_y2[m - 4][row] = ss;
        }
    }
}

// ---------------- mlr/sinh pointwise epilogue ------------------------------
__device__ __forceinline__ float fc_elem(int fc, int cl, float rb, float y2b, float g)
{
    const float nz = g_nz[fc][cl];
    const float s  = g / nz;                 // zhat_cl . x_b
    float alpha = tanhf(rb * nz);            // q = alpha * zhat (expmap0)
    float aa = fabsf(alpha);
    if (aa > MAXN) alpha *= MAXN / aa;       // _project(q)
    const float x2 = alpha * alpha;
    const float xy = -alpha * s;
    const float A  = 1.0f + 2.0f * xy + y2b;
    const float Bc = 1.0f - x2;
    const float den = fmaxf(1.0f + 2.0f * xy + x2 * y2b, EPSN);
    const float inv = 1.0f / den;
    float pa = (Bc * s - A * alpha) * inv;                                    // px . zhat
    float p2 = (A * A * x2 - 2.0f * A * Bc * alpha * s + Bc * Bc * y2b) * (inv * inv); // |px|^2
    float pn = fmaxf(sqrtf(p2), EPSN);
    if (pn > MAXN) { float f = MAXN / pn; pa *= f; p2 *= f * f; }             // _project(px)
    const float lam = 2.0f / (1.0f - p2);
    return sinhf(g_coef[fc][cl] * asinhf(pa * lam));                          // sinh(logit)
}

// ---------------- K1: 4 fused GEMMs (X . Z^T) + epilogue -------------------
__global__ void k1_gemm(const float* __restrict__ hidden, const float* __restrict__ hyp_x,
                        const float* __restrict__ Wz_z, const float* __restrict__ Wz_r,
                        const float* __restrict__ Uz_z, const float* __restrict__ Uz_r,
                        const float* __restrict__ Wr_z, const float* __restrict__ Wr_r,
                        const float* __restrict__ Ur_z, const float* __restrict__ Ur_r)
{
    const int fc = blockIdx.z;
    const float *X, *Z, *R;
    int ysel;
    if      (fc == 0) { X = hidden; Z = Wz_z; R = Wz_r; ysel = 0; }
    else if (fc == 1) { X = hyp_x;  Z = Uz_z; R = Uz_r; ysel = 1; }
    else if (fc == 2) { X = hidden; Z = Wr_z; R = Wr_r; ysel = 0; }
    else              { X = hyp_x;  Z = Ur_z; R = Ur_r; ysel = 1; }

    __shared__ float4 Xs[32][17];   // 32 rows x 64 k (pitch 17 float4 = conflict-free)
    __shared__ float4 Zs[32][17];

    const int b0 = blockIdx.y * 32, c0 = blockIdx.x * 32;
    const int tid = threadIdx.x;
    const int tx = tid & 15, ty = tid >> 4;

    float a00 = 0.f, a01 = 0.f, a10 = 0.f, a11 = 0.f;

    for (int kc = 0; kc < 256; kc += 64) {
        #pragma unroll
        for (int i = tid; i < 512; i += 256) {
            const int r = i >> 4, c = i & 15;
            Xs[r][c] = reinterpret_cast<const float4*>(X + (b0 + r) * 256 + kc)[c];
            Zs[r][c] = reinterpret_cast<const float4*>(Z + (c0 + r) * 256 + kc)[c];
        }
        __syncthreads();
        #pragma unroll
        for (int q = 0; q < 16; q++) {
            const float4 xA = Xs[ty][q],      xB = Xs[ty + 16][q];
            const float4 zA = Zs[tx][q],      zB = Zs[tx + 16][q];
            a00 = fmaf(xA.x, zA.x, a00); a00 = fmaf(xA.y, zA.y, a00);
            a00 = fmaf(xA.z, zA.z, a00); a00 = fmaf(xA.w, zA.w, a00);
            a01 = fmaf(xA.x, zB.x, a01); a01 = fmaf(xA.y, zB.y, a01);
            a01 = fmaf(xA.z, zB.z, a01); a01 = fmaf(xA.w, zB.w, a01);
            a10 = fmaf(xB.x, zA.x, a10); a10 = fmaf(xB.y, zA.y, a10);
            a10 = fmaf(xB.z, zA.z, a10); a10 = fmaf(xB.w, zA.w, a10);
            a11 = fmaf(xB.x, zB.x, a11); a11 = fmaf(xB.y, zB.y, a11);
            a11 = fmaf(xB.z, zB.z, a11); a11 = fmaf(xB.w, zB.w, a11);
        }
        __syncthreads();
    }

    const int bA = b0 + ty, bB = b0 + ty + 16;
    const int cA = c0 + tx, cB = c0 + tx + 16;
    const float rb0 = R[bA], rb1 = R[bB];
    const float y20 = g_y2[ysel][bA], y21 = g_y2[ysel][bB];

    g_w[fc][bA * 256 + cA] = fc_elem(fc, cA, rb0, y20, a00);
    g_w[fc][bA * 256 + cB] = fc_elem(fc, cB, rb0, y20, a01);
    g_w[fc][bB * 256 + cA] = fc_elem(fc, cA, rb1, y21, a10);
    g_w[fc][bB * 256 + cB] = fc_elem(fc, cB, rb1, y21, a11);
}

// ---------------- K1b: per-row scale = sqrt(sum w^2)+1 (deterministic) -----
__global__ void k1b_scale()
{
    __shared__ float sb[8];
    const int fc = blockIdx.y, row = blockIdx.x;
    const float w = g_w[fc][row * 256 + threadIdx.x];
    const float ss = brsum256(w * w, sb);
    if (threadIdx.x == 0) g_scale[fc][row] = sqrtf(ss) + 1.0f;
}

// ---------------- row-wise mobius_add with projection ----------------------
__device__ __forceinline__ float madd(float xe, float ye, float* sb, float* nrm)
{
    const float x2 = brsum256(xe * xe, sb);
    const float y2 = brsum256(ye * ye, sb);
    const float xy = brsum256(xe * ye, sb);
    const float A  = 1.0f + 2.0f * xy + y2;
    const float Bc = 1.0f - x2;
    const float den = fmaxf(1.0f + 2.0f * xy + x2 * y2, EPSN);
    float v = (A * xe + Bc * ye) / den;
    const float n2 = brsum256(v * v, sb);
    float n = fmaxf(sqrtf(n2), EPSN);
    if (n > MAXN) { v *= MAXN / n; n = MAXN; }
    *nrm = n;
    return v;
}

// ---------------- K2: one block per batch row: gates + cell update ---------
__global__ void k2_final(const float* __restrict__ hidden, const float* __restrict__ b_z,
                         const float* __restrict__ b_r, const float* __restrict__ b_h,
                         float* __restrict__ out)
{
    __shared__ float sb[8];
    const int b = blockIdx.x, j = threadIdx.x;
    const float CLIPV = (float)(1.0 - 1e-7);
    const float hid = hidden[b * 256 + j];
    float n;

    // z gate: mobius_add(mobius_add(Fz, Gz), b_z) -> sigmoid(logmap0)
    float F = g_scale[0][j] * g_w[0][b * 256 + j];
    float G = g_scale[1][j] * g_w[1][b * 256 + j];
    float t = madd(F, G, sb, &n);
    t = madd(t, b_z[j], sb, &n);
    float fac = atanhf(fminf(n, CLIPV)) / n;
    const float zg = 1.0f / (1.0f + expf(-fac * t));

    // r gate
    F = g_scale[2][j] * g_w[2][b * 256 + j];
    G = g_scale[3][j] * g_w[3][b * 256 + j];
    t = madd(F, G, sb, &n);
    t = madd(t, b_r[j], sb, &n);
    fac = atanhf(fminf(n, CLIPV)) / n;
    const float rg = 1.0f / (1.0f + expf(-fac * t));

    // h_tilde = mobius_add(r, b_h); mh = mobius_add(-hidden, h_tilde)
    const float ht = madd(rg, b_h[j], sb, &n);
    const float mh = madd(-hid, ht, sb, &n);

    // mobius_pointwise_mul(mh, zg)
    const float xn2  = brsum256(zg * zg, sb);
    const float wx   = mh * zg;
    const float wxn2 = brsum256(wx * wx, sb);
    const float xn   = fmaxf(sqrtf(xn2), EPSN);
    const float wxn  = fmaxf(sqrtf(wxn2), EPSN);
    const float tt   = atanhf(fminf(xn, CLIPV));
    const float f    = tanhf(wxn / xn * tt);   // f >= 0 == |result|
    float pw = f * wx / wxn;
    const float pn = fmaxf(f, EPSN);
    if (pn > MAXN) pw *= MAXN / pn;            // _project

    const float o = madd(hid, pw, sb, &n);     // mobius_add(hidden, pw)
    out[b * 256 + j] = o;
}

// ---------------- launch ----------------------------------------------------
extern "C" void kernel_launch(void* const* d_in, const int* in_sizes, int n_in,
                              void* d_out, int out_size)
{
    const float* hyp_x  = (const float*)d_in[0];
    const float* hidden = (const float*)d_in[1];
    const float* Wz_z   = (const float*)d_in[2];
    const float* Wz_r   = (const float*)d_in[3];
    const float* Uz_z   = (const float*)d_in[4];
    const float* Uz_r   = (const float*)d_in[5];
    const float* Wr_z   = (const float*)d_in[6];
    const float* Wr_r   = (const float*)d_in[7];
    const float* Ur_z   = (const float*)d_in[8];
    const float* Ur_r   = (const float*)d_in[9];
    // d_in[10..13] = Wh_z, Wh_r, Uh_z, Uh_r: dead code in reference, unused.
    const float* b_z    = (const float*)d_in[14];
    const float* b_r    = (const float*)d_in[15];
    const float* b_h    = (const float*)d_in[16];
    float* out = (float*)d_out;

    k0_stats<<<dim3(256, 6), 256>>>(Wz_z, Wz_r, Uz_z, Uz_r, Wr_z, Wr_r, Ur_z, Ur_r,
                                    hidden, hyp_x);
    k1_gemm<<<dim3(8, 8, 4), 256>>>(hidden, hyp_x, Wz_z, Wz_r, Uz_z, Uz_r,
                                    Wr_z, Wr_r, Ur_z, Ur_r);
    k1b_scale<<<dim3(256, 4), 256>>>();
    k2_final<<<256, 256>>>(hidden, b_z, b_r, b_h, out);
}

// round 2
// speedup vs baseline: 1.2384x; 1.2384x over previous
#include <cuda_runtime.h>
#include <math.h>

// B = H = IN = 256, c = 1. Dead code (Wh*/Uh*, r_point_h) skipped.

#define NB 256
#define MAXN 0.996f          // (1 - 4e-3)/sqrt(c)
#define EPSN 1e-15f
#define CLIPV 0.9999999f     // 1 - 1e-7 in f32

// ---------------- scratch ---------------------------------------------------
__device__ float g_w[4][NB * NB];     // w = sinh(mlr logits) per fc, [b][cl]
__device__ float g_scale[4][NB];      // sqrt(row-sumsq of w)+1
__device__ float g_nz[4][NB];         // ||z_cl||
__device__ float g_coef[4][NB];       // 2*||z_cl||/cosh(r_cl)^2
__device__ float g_y2[2][NB];         // ||x_b||^2 : [0]=hidden, [1]=hyp_x

// ---------------- fast math helpers -----------------------------------------
__device__ __forceinline__ float fsqrt_(float x) { float r; asm("sqrt.approx.f32 %0,%1;" : "=f"(r) : "f"(x)); return r; }
__device__ __forceinline__ float frcp_(float x)  { float r; asm("rcp.approx.f32 %0,%1;"  : "=f"(r) : "f"(x)); return r; }
__device__ __forceinline__ float ftanh_(float x) { float e = __expf(2.0f * x); return 1.0f - 2.0f * frcp_(e + 1.0f); }
__device__ __forceinline__ float fatanh_(float x){ return 0.5f * __logf((1.0f + x) * frcp_(1.0f - x)); }
__device__ __forceinline__ float fasinh_(float x){ float a = fabsf(x); float l = __logf(a + fsqrt_(fmaf(a, a, 1.0f))); return copysignf(l, x); }
__device__ __forceinline__ float fsinh_(float x) { float e = __expf(x); return 0.5f * (e - frcp_(e)); }
__device__ __forceinline__ float fsigm_(float x) { return frcp_(1.0f + __expf(-x)); }

__device__ __forceinline__ float wsum8(float v) {
    #pragma unroll
    for (int o = 16; o; o >>= 1) v += __shfl_xor_sync(0xffffffffu, v, o);
    return v;
}

// ---------------- K0: per-row stats (warp per row) ---------------------------
__global__ void k0_stats(const float* __restrict__ Wz_z, const float* __restrict__ Wz_r,
                         const float* __restrict__ Uz_z, const float* __restrict__ Uz_r,
                         const float* __restrict__ Wr_z, const float* __restrict__ Wr_r,
                         const float* __restrict__ Ur_z, const float* __restrict__ Ur_r,
                         const float* __restrict__ hidden, const float* __restrict__ hyp_x)
{
    const int gw = (blockIdx.x * blockDim.x + threadIdx.x) >> 5;
    const int lane = threadIdx.x & 31;
    const int m = gw >> 8, row = gw & 255;
    const float* p;
    if      (m == 0) p = Wz_z;
    else if (m == 1) p = Uz_z;
    else if (m == 2) p = Wr_z;
    else if (m == 3) p = Ur_z;
    else if (m == 4) p = hidden;
    else             p = hyp_x;

    float s = 0.0f;
    #pragma unroll
    for (int i = 0; i < 8; i++) { float v = p[row * NB + lane + 32 * i]; s = fmaf(v, v, s); }
    s = wsum8(s);
    if (lane == 0) {
        if (m < 4) {
            const float* R;
            if      (m == 0) R = Wz_r;
            else if (m == 1) R = Uz_r;
            else if (m == 2) R = Wr_r;
            else             R = Ur_r;
            float nz = sqrtf(s);
            g_nz[m][row] = nz;
            float ch = coshf(R[row]);
            g_coef[m][row] = 2.0f * nz / (ch * ch);
        } else {
            g_y2[m - 4][row] = s;
        }
    }
}

// ---------------- mlr/sinh epilogue ------------------------------------------
__device__ __forceinline__ float fc_elem(int fc, int cl, float rb, float y2b, float g)
{
    const float nz = g_nz[fc][cl];
    const float s  = g * frcp_(nz);
    float alpha = ftanh_(rb * nz);
    float aa = fabsf(alpha);
    if (aa > MAXN) alpha *= MAXN * frcp_(aa);
    const float x2 = alpha * alpha;
    const float xy = -alpha * s;
    const float A  = 1.0f + 2.0f * xy + y2b;
    const float Bc = 1.0f - x2;
    const float den = fmaxf(1.0f + 2.0f * xy + x2 * y2b, EPSN);
    const float inv = frcp_(den);
    float pa = (Bc * s - A * alpha) * inv;
    float p2 = (A * A * x2 - 2.0f * A * Bc * alpha * s + Bc * Bc * y2b) * (inv * inv);
    float pn = fmaxf(fsqrt_(fmaxf(p2, 0.0f)), EPSN);
    if (pn > MAXN) { float f = MAXN * frcp_(pn); pa *= f; p2 *= f * f; }
    const float lam = 2.0f * frcp_(1.0f - p2);
    return fsinh_(g_coef[fc][cl] * fasinh_(pa * lam));
}

// ---------------- K1: 4 fused GEMMs + epilogue -------------------------------
__global__ void k1_gemm(const float* __restrict__ hidden, const float* __restrict__ hyp_x,
                        const float* __restrict__ Wz_z, const float* __restrict__ Wz_r,
                        const float* __restrict__ Uz_z, const float* __restrict__ Uz_r,
                        const float* __restrict__ Wr_z, const float* __restrict__ Wr_r,
                        const float* __restrict__ Ur_z, const float* __restrict__ Ur_r)
{
    const int fc = blockIdx.z;
    const float *X, *Z, *R;
    int ysel;
    if      (fc == 0) { X = hidden; Z = Wz_z; R = Wz_r; ysel = 0; }
    else if (fc == 1) { X = hyp_x;  Z = Uz_z; R = Uz_r; ysel = 1; }
    else if (fc == 2) { X = hidden; Z = Wr_z; R = Wr_r; ysel = 0; }
    else              { X = hyp_x;  Z = Ur_z; R = Ur_r; ysel = 1; }

    __shared__ float4 Xs[32][17];
    __shared__ float4 Zs[32][17];

    const int b0 = blockIdx.y * 32, c0 = blockIdx.x * 32;
    const int tid = threadIdx.x;
    const int tx = tid & 15, ty = tid >> 4;

    float a00 = 0.f, a01 = 0.f, a10 = 0.f, a11 = 0.f;

    for (int kc = 0; kc < 256; kc += 64) {
        #pragma unroll
        for (int i = tid; i < 512; i += 256) {
            const int r = i >> 4, c = i & 15;
            Xs[r][c] = reinterpret_cast<const float4*>(X + (b0 + r) * 256 + kc)[c];
            Zs[r][c] = reinterpret_cast<const float4*>(Z + (c0 + r) * 256 + kc)[c];
        }
        __syncthreads();
        #pragma unroll
        for (int q = 0; q < 16; q++) {
            const float4 xA = Xs[ty][q],      xB = Xs[ty + 16][q];
            const float4 zA = Zs[tx][q],      zB = Zs[tx + 16][q];
            a00 = fmaf(xA.x, zA.x, a00); a00 = fmaf(xA.y, zA.y, a00);
            a00 = fmaf(xA.z, zA.z, a00); a00 = fmaf(xA.w, zA.w, a00);
            a01 = fmaf(xA.x, zB.x, a01); a01 = fmaf(xA.y, zB.y, a01);
            a01 = fmaf(xA.z, zB.z, a01); a01 = fmaf(xA.w, zB.w, a01);
            a10 = fmaf(xB.x, zA.x, a10); a10 = fmaf(xB.y, zA.y, a10);
            a10 = fmaf(xB.z, zA.z, a10); a10 = fmaf(xB.w, zA.w, a10);
            a11 = fmaf(xB.x, zB.x, a11); a11 = fmaf(xB.y, zB.y, a11);
            a11 = fmaf(xB.z, zB.z, a11); a11 = fmaf(xB.w, zB.w, a11);
        }
        __syncthreads();
    }

    const int bA = b0 + ty, bB = b0 + ty + 16;
    const int cA = c0 + tx, cB = c0 + tx + 16;
    const float rb0 = R[bA], rb1 = R[bB];
    const float y20 = g_y2[ysel][bA], y21 = g_y2[ysel][bB];

    g_w[fc][bA * 256 + cA] = fc_elem(fc, cA, rb0, y20, a00);
    g_w[fc][bA * 256 + cB] = fc_elem(fc, cB, rb0, y20, a01);
    g_w[fc][bB * 256 + cA] = fc_elem(fc, cA, rb1, y21, a10);
    g_w[fc][bB * 256 + cB] = fc_elem(fc, cB, rb1, y21, a11);
}

// ---------------- K1b: per-row scale (warp per row) --------------------------
__global__ void k1b_scale()
{
    const int gw = (blockIdx.x * blockDim.x + threadIdx.x) >> 5;
    const int lane = threadIdx.x & 31;
    const int fc = gw >> 8, row = gw & 255;
    float s = 0.0f;
    #pragma unroll
    for (int i = 0; i < 8; i++) { float w = g_w[fc][row * NB + lane + 32 * i]; s = fmaf(w, w, s); }
    s = wsum8(s);
    if (lane == 0) g_scale[fc][row] = sqrtf(s) + 1.0f;
}

// ---------------- madd scalar helper -----------------------------------------
struct MS { float A, B, inv, m, nc; };
__device__ __forceinline__ MS madds(float sxx, float syy, float sxy)
{
    MS r;
    r.A = 1.0f + 2.0f * sxy + syy;
    r.B = 1.0f - sxx;
    float den = fmaxf(1.0f + 2.0f * sxy + sxx * syy, EPSN);
    r.inv = frcp_(den);
    float n2 = (r.A * r.A * sxx + 2.0f * r.A * r.B * sxy + r.B * r.B * syy) * r.inv * r.inv;
    float n = fmaxf(fsqrt_(fmaxf(n2, 0.0f)), EPSN);
    r.m = (n > MAXN) ? MAXN * frcp_(n) : 1.0f;
    r.nc = fminf(n, MAXN);
    return r;
}

// ---------------- K2: warp per batch row -------------------------------------
__global__ void __launch_bounds__(256) k2_final(
    const float* __restrict__ hidden, const float* __restrict__ bz,
    const float* __restrict__ br, const float* __restrict__ bh,
    float* __restrict__ out)
{
    const int lane = threadIdx.x & 31;
    const int b = (blockIdx.x * blockDim.x + threadIdx.x) >> 5;

    float hid[8], bhv[8], bzv[8], brv[8], F0[8], G0[8], F1[8], G1[8];
    #pragma unroll
    for (int i = 0; i < 8; i++) {
        const int j = lane + 32 * i;
        hid[i] = hidden[b * NB + j];
        bhv[i] = bh[j]; bzv[i] = bz[j]; brv[i] = br[j];
        F0[i] = g_scale[0][j] * g_w[0][b * NB + j];
        G0[i] = g_scale[1][j] * g_w[1][b * NB + j];
        F1[i] = g_scale[2][j] * g_w[2][b * NB + j];
        G1[i] = g_scale[3][j] * g_w[3][b * NB + j];
    }

    // ---- reduction round 1: 15 sums ----
    float sFF0=0,sGG0=0,sFG0=0,sFb0=0,sGb0=0,sbb0=0;
    float sFF1=0,sGG1=0,sFG1=0,sFb1=0,sGb1=0,sbb1=0;
    float shh=0,sbhbh=0,shbh=0;
    #pragma unroll
    for (int i = 0; i < 8; i++) {
        sFF0=fmaf(F0[i],F0[i],sFF0); sGG0=fmaf(G0[i],G0[i],sGG0); sFG0=fmaf(F0[i],G0[i],sFG0);
        sFb0=fmaf(F0[i],bzv[i],sFb0); sGb0=fmaf(G0[i],bzv[i],sGb0); sbb0=fmaf(bzv[i],bzv[i],sbb0);
        sFF1=fmaf(F1[i],F1[i],sFF1); sGG1=fmaf(G1[i],G1[i],sGG1); sFG1=fmaf(F1[i],G1[i],sFG1);
        sFb1=fmaf(F1[i],brv[i],sFb1); sGb1=fmaf(G1[i],brv[i],sGb1); sbb1=fmaf(brv[i],brv[i],sbb1);
        shh=fmaf(hid[i],hid[i],shh); sbhbh=fmaf(bhv[i],bhv[i],sbhbh); shbh=fmaf(hid[i],bhv[i],shbh);
    }
    #pragma unroll
    for (int o = 16; o; o >>= 1) {
        sFF0+=__shfl_xor_sync(~0u,sFF0,o); sGG0+=__shfl_xor_sync(~0u,sGG0,o); sFG0+=__shfl_xor_sync(~0u,sFG0,o);
        sFb0+=__shfl_xor_sync(~0u,sFb0,o); sGb0+=__shfl_xor_sync(~0u,sGb0,o); sbb0+=__shfl_xor_sync(~0u,sbb0,o);
        sFF1+=__shfl_xor_sync(~0u,sFF1,o); sGG1+=__shfl_xor_sync(~0u,sGG1,o); sFG1+=__shfl_xor_sync(~0u,sFG1,o);
        sFb1+=__shfl_xor_sync(~0u,sFb1,o); sGb1+=__shfl_xor_sync(~0u,sGb1,o); sbb1+=__shfl_xor_sync(~0u,sbb1,o);
        shh +=__shfl_xor_sync(~0u,shh,o);  sbhbh+=__shfl_xor_sync(~0u,sbhbh,o); shbh+=__shfl_xor_sync(~0u,shbh,o);
    }

    // ---- z gate (closed form) ----
    MS z1 = madds(sFF0, sGG0, sFG0);
    float zcF = z1.m * z1.inv * z1.A, zcG = z1.m * z1.inv * z1.B;
    MS z2 = madds(z1.nc * z1.nc, sbb0, zcF * sFb0 + zcG * sGb0);
    float k2a = z2.m * z2.inv * z2.A, k2b = z2.m * z2.inv * z2.B;
    float facz = fatanh_(z2.nc) * frcp_(z2.nc);
    float zg[8];
    #pragma unroll
    for (int i = 0; i < 8; i++)
        zg[i] = fsigm_(facz * (k2a * (zcF * F0[i] + zcG * G0[i]) + k2b * bzv[i]));

    // ---- r gate ----
    MS r1 = madds(sFF1, sGG1, sFG1);
    float rcF = r1.m * r1.inv * r1.A, rcG = r1.m * r1.inv * r1.B;
    MS r2 = madds(r1.nc * r1.nc, sbb1, rcF * sFb1 + rcG * sGb1);
    float l2a = r2.m * r2.inv * r2.A, l2b = r2.m * r2.inv * r2.B;
    float facr = fatanh_(r2.nc) * frcp_(r2.nc);
    float rg[8];
    #pragma unroll
    for (int i = 0; i < 8; i++)
        rg[i] = fsigm_(facr * (l2a * (rcF * F1[i] + rcG * G1[i]) + l2b * brv[i]));

    // ---- reduction round 2: 4 sums ----
    float srr=0, srbh=0, shr=0, szz=0;
    #pragma unroll
    for (int i = 0; i < 8; i++) {
        srr=fmaf(rg[i],rg[i],srr); srbh=fmaf(rg[i],bhv[i],srbh);
        shr=fmaf(hid[i],rg[i],shr); szz=fmaf(zg[i],zg[i],szz);
    }
    #pragma unroll
    for (int o = 16; o; o >>= 1) {
        srr+=__shfl_xor_sync(~0u,srr,o); srbh+=__shfl_xor_sync(~0u,srbh,o);
        shr+=__shfl_xor_sync(~0u,shr,o); szz+=__shfl_xor_sync(~0u,szz,o);
    }

    // ---- h_tilde = madd(rg, bh); mh = madd(-hid, ht) ----
    MS h3 = madds(srr, sbhbh, srbh);
    float hA = h3.m * h3.inv * h3.A, hB = h3.m * h3.inv * h3.B;
    float sht_h = hA * shr + hB * shbh;                 // hid . ht
    MS h4 = madds(shh, h3.nc * h3.nc, -sht_h);
    float mA = -h4.m * h4.inv * h4.A;                   // coef on hid
    float mR =  h4.m * h4.inv * h4.B * hA;              // coef on rg
    float mB =  h4.m * h4.inv * h4.B * hB;              // coef on bh

    // ---- reduction round 3: Sum wx^2, Sum hid*wx ----
    float swx = 0, shwx = 0;
    #pragma unroll
    for (int i = 0; i < 8; i++) {
        float wx = (mA * hid[i] + mR * rg[i] + mB * bhv[i]) * zg[i];
        swx = fmaf(wx, wx, swx);
        shwx = fmaf(hid[i], wx, shwx);
    }
    #pragma unroll
    for (int o = 16; o; o >>= 1) {
        swx += __shfl_xor_sync(~0u, swx, o);
        shwx += __shfl_xor_sync(~0u, shwx, o);
    }

    // ---- mobius pointwise mul + final add (closed form) ----
    float xn  = fmaxf(fsqrt_(szz), EPSN);
    float wxn = fmaxf(fsqrt_(swx), EPSN);
    float tt  = fatanh_(fminf(xn, CLIPV));
    float f   = ftanh_(wxn * frcp_(xn) * tt);
    float pn  = fmaxf(f, EPSN);
    float cf  = f * frcp_(wxn);
    if (pn > MAXN) cf *= MAXN * frcp_(pn);
    float pnc = fminf(pn, MAXN);

    MS o5 = madds(shh, pnc * pnc, cf * shwx);
    float oH = o5.m * o5.inv * o5.A, oP = o5.m * o5.inv * o5.B * cf;

    #pragma unroll
    for (int i = 0; i < 8; i++) {
        const int j = lane + 32 * i;
        float wx = (mA * hid[i] + mR * rg[i] + mB * bhv[i]) * zg[i];
        out[b * NB + j] = oH * hid[i] + oP * wx;
    }
}

// ---------------- launch ------------------------------------------------------
extern "C" void kernel_launch(void* const* d_in, const int* in_sizes, int n_in,
                              void* d_out, int out_size)
{
    const float* hyp_x  = (const float*)d_in[0];
    const float* hidden = (const float*)d_in[1];
    const float* Wz_z   = (const float*)d_in[2];
    const float* Wz_r   = (const float*)d_in[3];
    const float* Uz_z   = (const float*)d_in[4];
    const float* Uz_r   = (const float*)d_in[5];
    const float* Wr_z   = (const float*)d_in[6];
    const float* Wr_r   = (const float*)d_in[7];
    const float* Ur_z   = (const float*)d_in[8];
    const float* Ur_r   = (const float*)d_in[9];
    const float* b_z    = (const float*)d_in[14];
    const float* b_r    = (const float*)d_in[15];
    const float* b_h    = (const float*)d_in[16];
    float* out = (float*)d_out;

    k0_stats<<<192, 256>>>(Wz_z, Wz_r, Uz_z, Uz_r, Wr_z, Wr_r, Ur_z, Ur_r, hidden, hyp_x);
    k1_gemm<<<dim3(8, 8, 4), 256>>>(hidden, hyp_x, Wz_z, Wz_r, Uz_z, Uz_r,
                                    Wr_z, Wr_r, Ur_z, Ur_r);
    k1b_scale<<<128, 256>>>();
    k2_final<<<32, 256>>>(hidden, b_z, b_r, b_h, out);
}